// round 10
// baseline (speedup 1.0000x reference)
#include <cuda_runtime.h>

#define N_PROPS   100000
#define NCLS      91
#define NFG       90
#define CAPC      8192
#define TOPKC     1000
#define SCORE_TH  0.05f
#define CLIP_W    1332.0f
#define CLIP_H    799.0f
#define XFORM_CLIP 4.135166556742356f   // log(1000/16)

typedef unsigned long long ull;

// ---------------- scratch ----------------
__device__ ull    g_cand  [NFG * CAPC];
__device__ int    g_count [NFG];
__device__ float4 g_cboxes4[NFG * TOPKC];
__device__ float  g_cscore[NFG * TOPKC];
__device__ ull    g_merge [NFG * 100];

// ---------------- stage 0: per-replay init ----------------
__global__ void init_kernel(float* __restrict__ out) {
    int t = threadIdx.x;
    if (t < NFG) g_count[t] = 0;
    if (t < 600) out[t] = (t >= 400 && t < 500) ? -1.0f : 0.0f;
}

// FMA-pipe exp (Cody-Waite + degree-6 minimax), ~2ulp.
__device__ __forceinline__ float exp_poly(float x) {
    float t  = x * 1.4426950408889634f;
    float fn = rintf(t);
    int   n  = (int)fn;
    float r  = fmaf(fn, -0.693359375f, x);
    r        = fmaf(fn,  2.12194440e-4f, r);
    float p  = 1.9875691500E-4f;
    p = fmaf(p, r, 1.3981999507E-3f);
    p = fmaf(p, r, 8.3334519073E-3f);
    p = fmaf(p, r, 4.1665795894E-2f);
    p = fmaf(p, r, 1.6666665459E-1f);
    p = fmaf(p, r, 5.0000001201E-1f);
    p = fmaf(p * r, r, r) + 1.0f;
    return p * __uint_as_float((unsigned)((n + 127) << 23));
}

// ---------------- stage 1: fused softmax + threshold compaction ----------------
// Warp-aggregated candidate emission: each warp iteration handles exactly one
// class (c uniform across the warp, r == lane), so one ballot + one lane-0
// atomicAdd replaces 32 serialized gmem atomics on g_count[c].
__global__ void softmax_compact_kernel(const float* __restrict__ logits) {
    __shared__ float sm[32][92];
    __shared__ float sinv[32];
    int base = blockIdx.x * 32;

    for (int t = threadIdx.x; t < 32 * 91; t += 256) {
        int r = t / 91, c = t - r * 91;
        sm[r][c] = logits[(base + r) * 91 + c];
    }
    __syncthreads();

    int warp = threadIdx.x >> 5, lane = threadIdx.x & 31;
    for (int r = warp; r < 32; r += 8) {
        float e0 = __expf(sm[r][lane]);                   // MUFU pipe
        float e1 = __expf(sm[r][lane + 32]);              // MUFU pipe
        float e2 = 0.0f;
        if (lane < 27) e2 = exp_poly(sm[r][lane + 64]);   // FMA pipe
        sm[r][lane]      = e0;
        sm[r][lane + 32] = e1;
        if (lane < 27) sm[r][lane + 64] = e2;
        float sum = e0 + e1 + e2;
        #pragma unroll
        for (int d = 16; d > 0; d >>= 1)
            sum += __shfl_xor_sync(0xffffffffu, sum, d);
        if (lane == 0) sinv[r] = 1.0f / sum;
    }
    __syncthreads();

    for (int t = threadIdx.x; t < NFG * 32; t += 256) {
        int c = t >> 5;       // fg class, uniform across the warp
        int r = t & 31;       // == lane (stride 256 is a multiple of 32)
        float v = sm[r][c + 1] * sinv[r];
        bool p = v > SCORE_TH;
        unsigned ball = __ballot_sync(0xffffffffu, p);
        int pos = 0;
        if (lane == 0 && ball) pos = atomicAdd(&g_count[c], __popc(ball));
        pos = __shfl_sync(0xffffffffu, pos, 0);
        if (p) {
            int mypos = pos + __popc(ball & ((1u << lane) - 1u));
            if (mypos < CAPC)
                g_cand[c * CAPC + mypos] =
                    ((ull)__float_as_uint(v) << 32) | (unsigned)(~(base + r));
        }
    }
}

// ---------------- stage 2: histogram-select + small bitonic + fused decode ----
#define SORT_SMEM (CAPC*8 + 1024*4 + 16)
__global__ void __launch_bounds__(1024) sortselect_kernel(
        const float* __restrict__ reg, const float* __restrict__ prop) {
    extern __shared__ unsigned char ssm[];
    ull* sk    = (ull*)ssm;                  // up to CAPC selected keys
    int* hist  = (int*)(sk + CAPC);          // 1024 buckets
    int* sinfo = hist + 1024;                // [0]=B, [1]=selcnt
    int c = blockIdx.x, tid = threadIdx.x;
    int count = min(g_count[c], CAPC);
    int want  = min(count, TOPKC);

    hist[tid] = 0;
    if (tid == 0) { sinfo[0] = 0; sinfo[1] = 0; }
    __syncthreads();

    for (int t = tid; t < count; t += 1024) {
        ull k = g_cand[c * CAPC + t];
        int b = (int)(k >> 48) - 0x3D00;
        b = max(0, min(1023, b));
        atomicAdd(&hist[b], 1);
    }
    __syncthreads();

    // warp 0: highest bucket B with suffix-count >= want
    if (tid < 32) {
        int base = 1023 - tid * 32;          // lane 0 covers the top buckets
        int lsum = 0;
        #pragma unroll
        for (int q = 0; q < 32; q++) lsum += hist[base - q];
        int incl = lsum;
        #pragma unroll
        for (int d = 1; d < 32; d <<= 1) {
            int v = __shfl_up_sync(0xffffffffu, incl, d);
            if (tid >= d) incl += v;
        }
        int excl = incl - lsum;
        bool has = (excl < want) && (excl + lsum >= want);
        unsigned ball = __ballot_sync(0xffffffffu, has);
        if (ball) {
            int selLane = __ffs(ball) - 1;
            if ((int)tid == selLane) {
                int cum = excl, b = base;
                for (int q = 0; q < 32; q++) {
                    cum += hist[base - q];
                    if (cum >= want) { b = base - q; break; }
                }
                sinfo[0] = b;
            }
        }
    }
    __syncthreads();

    int B = sinfo[0];
    for (int t = tid; t < count; t += 1024) {
        ull k = g_cand[c * CAPC + t];
        int b = (int)(k >> 48) - 0x3D00;
        b = max(0, min(1023, b));
        if (b >= B) {
            int p = atomicAdd(&sinfo[1], 1);
            sk[p] = k;          // p < count <= CAPC always
        }
    }
    __syncthreads();

    int selcnt = sinfo[1];
    int S = 1024;
    while (S < selcnt) S <<= 1;
    for (int t = tid; t < S; t += 1024)
        if (t >= selcnt) sk[t] = 0ull;
    __syncthreads();

    for (int k = 2; k <= S; k <<= 1) {
        for (int j = k >> 1; j > 0; j >>= 1) {
            for (int t = tid; t < S; t += 1024) {
                int ixj = t ^ j;
                if (ixj > t) {
                    ull a = sk[t], b = sk[ixj];
                    bool up = (t & k) == 0;
                    if (up ? (a < b) : (a > b)) { sk[t] = b; sk[ixj] = a; }
                }
            }
            __syncthreads();
        }
    }

    // fused decode of top-1000
    if (tid < TOPKC) {
        int g = c * TOPKC + tid;
        ull key = sk[tid];
        if (key == 0ull) {
            g_cscore[g] = -1.0f;
            g_cboxes4[g] = make_float4(0.f, 0.f, 0.f, 0.f);
        } else {
            unsigned idx = ~(unsigned)(key & 0xffffffffu);
            float score = __uint_as_float((unsigned)(key >> 32));
            const float* pb = prop + (size_t)idx * 4;
            float x1 = pb[0], y1 = pb[1], x2 = pb[2], y2 = pb[3];
            float w = x2 - x1 + 1.0f, h = y2 - y1 + 1.0f;
            float cx = x1 + 0.5f * w, cy = y1 + 0.5f * h;
            const float* d = reg + (size_t)idx * (NCLS * 4) + (size_t)(c + 1) * 4;
            float dx = d[0] * 0.1f;
            float dy = d[1] * 0.1f;
            float dw = fminf(d[2] * 0.2f, XFORM_CLIP);
            float dh = fminf(d[3] * 0.2f, XFORM_CLIP);
            float pcx = dx * w + cx, pcy = dy * h + cy;
            float pw = __expf(dw) * w, ph = __expf(dh) * h;
            float4 o;
            o.x = fminf(fmaxf(pcx - 0.5f * pw, 0.0f), CLIP_W);
            o.y = fminf(fmaxf(pcy - 0.5f * ph, 0.0f), CLIP_H);
            o.z = fminf(fmaxf(pcx + 0.5f * pw - 1.0f, 0.0f), CLIP_W);
            o.w = fminf(fmaxf(pcy + 0.5f * ph - 1.0f, 0.0f), CLIP_H);
            g_cboxes4[g] = o;
            g_cscore[g] = score;
        }
    }
}

// ---------------- stage 3: warp-per-class NMS, zero block barriers ------------
// One warp owns one class. Boxes in smem as SoA; lane l owns boxes j == l mod 32
// (bit k of its 32-bit alive register = box k*32+l). Greedy round: warp-min via
// shfl to find next live box, then each lane ffs-iterates only its ALIVE bits
// against the current box. Early stop at 100 kept. All comms are warp shuffles.
#define NMS_WARPS 4
#define NMS_SMEM  (NMS_WARPS * 6 * TOPKC * 4)   // x1,y1,x2,y2,area,score
__global__ void __launch_bounds__(NMS_WARPS * 32) nms_kernel() {
    extern __shared__ float nsm[];
    int wid = threadIdx.x >> 5, lane = threadIdx.x & 31;
    int c = blockIdx.x * NMS_WARPS + wid;
    if (c >= NFG) return;

    float* sx1 = nsm + wid * 6 * TOPKC;
    float* sy1 = sx1 + TOPKC;
    float* sx2 = sy1 + TOPKC;
    float* sy2 = sx2 + TOPKC;
    float* sar = sy2 + TOPKC;
    float* ssc = sar + TOPKC;

    // load + SoA transpose + alive init
    unsigned alive = 0u;
    #pragma unroll
    for (int k = 0; k < 32; k++) {
        int j = (k << 5) + lane;
        if (j < TOPKC) {
            float4 b = g_cboxes4[c * TOPKC + j];
            sx1[j] = b.x; sy1[j] = b.y; sx2[j] = b.z; sy2[j] = b.w;
            sar[j] = (b.z - b.x + 1.0f) * (b.w - b.y + 1.0f);
            float s = g_cscore[c * TOPKC + j];
            ssc[j] = s;
            if (s > SCORE_TH) alive |= 1u << k;
        }
    }
    __syncwarp();

    int nk = 0;
    while (nk < 100) {
        // find minimum alive index across the warp
        int cand = alive ? (((__ffs(alive) - 1) << 5) | lane) : 0x7fffffff;
        #pragma unroll
        for (int d = 16; d > 0; d >>= 1)
            cand = min(cand, __shfl_xor_sync(0xffffffffu, cand, d));
        if (cand == 0x7fffffff) break;
        int cur = cand;
        if (lane == (cur & 31)) alive &= ~(1u << (cur >> 5));

        float cx1 = sx1[cur], cy1 = sy1[cur];      // broadcast LDS
        float cx2 = sx2[cur], cy2 = sy2[cur];
        float ac  = sar[cur];
        if (lane == 0) {
            int flat = c * TOPKC + cur;
            g_merge[c * 100 + nk] =
                ((ull)__float_as_uint(ssc[cur]) << 32) | (unsigned)(~flat);
        }
        nk++;

        // suppress: iterate only MY alive bits (all alive j are > cur)
        unsigned rem = alive;
        while (rem) {
            int k = __ffs(rem) - 1;
            rem &= rem - 1;
            int j = (k << 5) + lane;
            float iw = fminf(cx2, sx2[j]) - fmaxf(cx1, sx1[j]) + 1.0f;
            float ih = fminf(cy2, sy2[j]) - fmaxf(cy1, sy1[j]) + 1.0f;
            float inter = fmaxf(iw, 0.0f) * fmaxf(ih, 0.0f);
            if (3.0f * inter > ac + sar[j])        // iou > 0.5
                alive &= ~(1u << k);
        }
        __syncwarp();
    }

    // pad remaining merge slots
    for (int p = nk + lane; p < 100; p += 32)
        g_merge[c * 100 + p] = 0ull;
}

// ---------------- stage 4: global top-100 via histogram-select + rank ---------
#define MERGE_SMEM (9000*8 + 1024*4 + 1024*8 + 16)
__global__ void __launch_bounds__(1024) merge_kernel(float* __restrict__ out) {
    extern __shared__ unsigned char msm[];
    ull* sk    = (ull*)msm;                 // 9000 keys
    int* hist  = (int*)(sk + 9000);         // 1024 buckets
    ull* ssel  = (ull*)(hist + 1024);       // selected (<=1024)
    int* sinfo = (int*)(ssel + 1024);       // [0]=B, [1]=scnt
    int tid = threadIdx.x;

    for (int t = tid; t < NFG * 100; t += 1024) sk[t] = g_merge[t];
    hist[tid] = 0;
    if (tid == 0) { sinfo[0] = 0; sinfo[1] = 0; }
    __syncthreads();

    for (int t = tid; t < NFG * 100; t += 1024) {
        ull k = sk[t];
        if (k) {
            int b = (int)(k >> 48) - 0x3D00;
            b = max(0, min(1023, b));
            atomicAdd(&hist[b], 1);
        }
    }
    __syncthreads();

    if (tid < 32) {
        int base = 1023 - tid * 32;
        int lsum = 0;
        #pragma unroll
        for (int q = 0; q < 32; q++) lsum += hist[base - q];
        int incl = lsum;
        #pragma unroll
        for (int d = 1; d < 32; d <<= 1) {
            int v = __shfl_up_sync(0xffffffffu, incl, d);
            if (tid >= d) incl += v;
        }
        int excl = incl - lsum;
        bool has = (excl < 100) && (excl + lsum >= 100);
        unsigned ball = __ballot_sync(0xffffffffu, has);
        if (ball) {
            int selLane = __ffs(ball) - 1;
            if ((int)tid == selLane) {
                int cum = excl, b = base;
                for (int q = 0; q < 32; q++) {
                    cum += hist[base - q];
                    if (cum >= 100) { b = base - q; break; }
                }
                sinfo[0] = b;
            }
        }
    }
    __syncthreads();

    int B = sinfo[0];
    for (int t = tid; t < NFG * 100; t += 1024) {
        ull k = sk[t];
        if (k) {
            int b = (int)(k >> 48) - 0x3D00;
            b = max(0, min(1023, b));
            if (b >= B) {
                int pos = atomicAdd(&sinfo[1], 1);
                if (pos < 1024) ssel[pos] = k;
            }
        }
    }
    __syncthreads();

    int scnt = min(sinfo[1], 1024);
    if (tid < scnt) {
        ull my = ssel[tid];
        int cnt = 0;
        for (int x = 0; x < scnt; x++) cnt += (ssel[x] > my);
        if (cnt < 100) {                     // exact global rank (keys unique)
            int flat = (int)(~(unsigned)(my & 0xffffffffu));
            float sc = __uint_as_float((unsigned)(my >> 32));
            float4 b = g_cboxes4[flat];
            out[cnt * 4 + 0] = b.x;
            out[cnt * 4 + 1] = b.y;
            out[cnt * 4 + 2] = b.z;
            out[cnt * 4 + 3] = b.w;
            out[400 + cnt] = sc;
            out[500 + cnt] = (float)(flat / TOPKC + 1);
        }
    }
}

// ---------------- launch ----------------
extern "C" void kernel_launch(void* const* d_in, const int* in_sizes, int n_in,
                              void* d_out, int out_size) {
    const float* logits = nullptr;
    const float* reg    = nullptr;
    const float* prop   = nullptr;
    for (int i = 0; i < n_in; i++) {
        if (in_sizes[i] == N_PROPS * NCLS)          logits = (const float*)d_in[i];
        else if (in_sizes[i] == N_PROPS * NCLS * 4) reg    = (const float*)d_in[i];
        else if (in_sizes[i] == N_PROPS * 4)        prop   = (const float*)d_in[i];
    }
    if (!logits) logits = (const float*)d_in[0];
    if (!reg)    reg    = (const float*)d_in[1];
    if (!prop)   prop   = (const float*)d_in[2];

    cudaFuncSetAttribute(sortselect_kernel,
                         cudaFuncAttributeMaxDynamicSharedMemorySize, SORT_SMEM);
    cudaFuncSetAttribute(nms_kernel,
                         cudaFuncAttributeMaxDynamicSharedMemorySize, NMS_SMEM);
    cudaFuncSetAttribute(merge_kernel,
                         cudaFuncAttributeMaxDynamicSharedMemorySize, MERGE_SMEM);

    init_kernel<<<1, 640>>>((float*)d_out);
    softmax_compact_kernel<<<N_PROPS / 32, 256>>>(logits);
    sortselect_kernel<<<NFG, 1024, SORT_SMEM>>>(reg, prop);
    nms_kernel<<<(NFG + NMS_WARPS - 1) / NMS_WARPS, NMS_WARPS * 32, NMS_SMEM>>>();
    merge_kernel<<<1, 1024, MERGE_SMEM>>>((float*)d_out);
}

// round 12
// speedup vs baseline: 1.8754x; 1.8754x over previous
#include <cuda_runtime.h>

#define N_PROPS   100000
#define NCLS      91
#define NFG       90
#define CAPC      8192
#define TOPKC     1000
#define SCORE_TH  0.05f
#define CLIP_W    1332.0f
#define CLIP_H    799.0f
#define XFORM_CLIP 4.135166556742356f   // log(1000/16)

typedef unsigned long long ull;

// ---------------- scratch ----------------
__device__ ull    g_cand  [NFG * CAPC];
__device__ int    g_count [NFG];
__device__ float4 g_cboxes4[NFG * TOPKC];
__device__ float  g_cscore[NFG * TOPKC];
__device__ ull    g_merge [NFG * 100];

// ---------------- stage 0: per-replay init ----------------
__global__ void init_kernel(float* __restrict__ out) {
    int t = threadIdx.x;
    if (t < NFG) g_count[t] = 0;
    if (t < 600) out[t] = (t >= 400 && t < 500) ? -1.0f : 0.0f;
}

// FMA-pipe exp (Cody-Waite + degree-6 minimax), ~2ulp.
__device__ __forceinline__ float exp_poly(float x) {
    float t  = x * 1.4426950408889634f;
    float fn = rintf(t);
    int   n  = (int)fn;
    float r  = fmaf(fn, -0.693359375f, x);
    r        = fmaf(fn,  2.12194440e-4f, r);
    float p  = 1.9875691500E-4f;
    p = fmaf(p, r, 1.3981999507E-3f);
    p = fmaf(p, r, 8.3334519073E-3f);
    p = fmaf(p, r, 4.1665795894E-2f);
    p = fmaf(p, r, 1.6666665459E-1f);
    p = fmaf(p, r, 5.0000001201E-1f);
    p = fmaf(p * r, r, r) + 1.0f;
    return p * __uint_as_float((unsigned)((n + 127) << 23));
}

// ---------------- stage 1: fused softmax + threshold compaction ----------------
// Warp-aggregated candidate emission (one lane-0 atomic per warp-round instead
// of 32 serialized gmem atomics on g_count[c]) — measured ~90us win in R10.
__global__ void softmax_compact_kernel(const float* __restrict__ logits) {
    __shared__ float sm[32][92];
    __shared__ float sinv[32];
    int base = blockIdx.x * 32;

    for (int t = threadIdx.x; t < 32 * 91; t += 256) {
        int r = t / 91, c = t - r * 91;
        sm[r][c] = logits[(base + r) * 91 + c];
    }
    __syncthreads();

    int warp = threadIdx.x >> 5, lane = threadIdx.x & 31;
    for (int r = warp; r < 32; r += 8) {
        float e0 = __expf(sm[r][lane]);                   // MUFU pipe
        float e1 = __expf(sm[r][lane + 32]);              // MUFU pipe
        float e2 = 0.0f;
        if (lane < 27) e2 = exp_poly(sm[r][lane + 64]);   // FMA pipe
        sm[r][lane]      = e0;
        sm[r][lane + 32] = e1;
        if (lane < 27) sm[r][lane + 64] = e2;
        float sum = e0 + e1 + e2;
        #pragma unroll
        for (int d = 16; d > 0; d >>= 1)
            sum += __shfl_xor_sync(0xffffffffu, sum, d);
        if (lane == 0) sinv[r] = 1.0f / sum;
    }
    __syncthreads();

    for (int t = threadIdx.x; t < NFG * 32; t += 256) {
        int c = t >> 5;       // fg class, uniform across the warp
        int r = t & 31;       // == lane (stride 256 is a multiple of 32)
        float v = sm[r][c + 1] * sinv[r];
        bool p = v > SCORE_TH;
        unsigned ball = __ballot_sync(0xffffffffu, p);
        int pos = 0;
        if (lane == 0 && ball) pos = atomicAdd(&g_count[c], __popc(ball));
        pos = __shfl_sync(0xffffffffu, pos, 0);
        if (p) {
            int mypos = pos + __popc(ball & ((1u << lane) - 1u));
            if (mypos < CAPC)
                g_cand[c * CAPC + mypos] =
                    ((ull)__float_as_uint(v) << 32) | (unsigned)(~(base + r));
        }
    }
}

// ---------------- stage 2: histogram-select + small bitonic + fused decode ----
#define SORT_SMEM (CAPC*8 + 1024*4 + 16)
__global__ void __launch_bounds__(1024) sortselect_kernel(
        const float* __restrict__ reg, const float* __restrict__ prop) {
    extern __shared__ unsigned char ssm[];
    ull* sk    = (ull*)ssm;                  // up to CAPC selected keys
    int* hist  = (int*)(sk + CAPC);          // 1024 buckets
    int* sinfo = hist + 1024;                // [0]=B, [1]=selcnt
    int c = blockIdx.x, tid = threadIdx.x;
    int count = min(g_count[c], CAPC);
    int want  = min(count, TOPKC);

    hist[tid] = 0;
    if (tid == 0) { sinfo[0] = 0; sinfo[1] = 0; }
    __syncthreads();

    for (int t = tid; t < count; t += 1024) {
        ull k = g_cand[c * CAPC + t];
        int b = (int)(k >> 48) - 0x3D00;
        b = max(0, min(1023, b));
        atomicAdd(&hist[b], 1);
    }
    __syncthreads();

    // warp 0: highest bucket B with suffix-count >= want
    if (tid < 32) {
        int base = 1023 - tid * 32;          // lane 0 covers the top buckets
        int lsum = 0;
        #pragma unroll
        for (int q = 0; q < 32; q++) lsum += hist[base - q];
        int incl = lsum;
        #pragma unroll
        for (int d = 1; d < 32; d <<= 1) {
            int v = __shfl_up_sync(0xffffffffu, incl, d);
            if (tid >= d) incl += v;
        }
        int excl = incl - lsum;
        bool has = (excl < want) && (excl + lsum >= want);
        unsigned ball = __ballot_sync(0xffffffffu, has);
        if (ball) {
            int selLane = __ffs(ball) - 1;
            if ((int)tid == selLane) {
                int cum = excl, b = base;
                for (int q = 0; q < 32; q++) {
                    cum += hist[base - q];
                    if (cum >= want) { b = base - q; break; }
                }
                sinfo[0] = b;
            }
        }
    }
    __syncthreads();

    int B = sinfo[0];
    for (int t = tid; t < count; t += 1024) {
        ull k = g_cand[c * CAPC + t];
        int b = (int)(k >> 48) - 0x3D00;
        b = max(0, min(1023, b));
        if (b >= B) {
            int p = atomicAdd(&sinfo[1], 1);
            sk[p] = k;          // p < count <= CAPC always
        }
    }
    __syncthreads();

    int selcnt = sinfo[1];
    int S = 1024;
    while (S < selcnt) S <<= 1;
    for (int t = tid; t < S; t += 1024)
        if (t >= selcnt) sk[t] = 0ull;
    __syncthreads();

    for (int k = 2; k <= S; k <<= 1) {
        for (int j = k >> 1; j > 0; j >>= 1) {
            for (int t = tid; t < S; t += 1024) {
                int ixj = t ^ j;
                if (ixj > t) {
                    ull a = sk[t], b = sk[ixj];
                    bool up = (t & k) == 0;
                    if (up ? (a < b) : (a > b)) { sk[t] = b; sk[ixj] = a; }
                }
            }
            __syncthreads();
        }
    }

    // fused decode of top-1000
    if (tid < TOPKC) {
        int g = c * TOPKC + tid;
        ull key = sk[tid];
        if (key == 0ull) {
            g_cscore[g] = -1.0f;
            g_cboxes4[g] = make_float4(0.f, 0.f, 0.f, 0.f);
        } else {
            unsigned idx = ~(unsigned)(key & 0xffffffffu);
            float score = __uint_as_float((unsigned)(key >> 32));
            const float* pb = prop + (size_t)idx * 4;
            float x1 = pb[0], y1 = pb[1], x2 = pb[2], y2 = pb[3];
            float w = x2 - x1 + 1.0f, h = y2 - y1 + 1.0f;
            float cx = x1 + 0.5f * w, cy = y1 + 0.5f * h;
            const float* d = reg + (size_t)idx * (NCLS * 4) + (size_t)(c + 1) * 4;
            float dx = d[0] * 0.1f;
            float dy = d[1] * 0.1f;
            float dw = fminf(d[2] * 0.2f, XFORM_CLIP);
            float dh = fminf(d[3] * 0.2f, XFORM_CLIP);
            float pcx = dx * w + cx, pcy = dy * h + cy;
            float pw = __expf(dw) * w, ph = __expf(dh) * h;
            float4 o;
            o.x = fminf(fmaxf(pcx - 0.5f * pw, 0.0f), CLIP_W);
            o.y = fminf(fmaxf(pcy - 0.5f * ph, 0.0f), CLIP_H);
            o.z = fminf(fmaxf(pcx + 0.5f * pw - 1.0f, 0.0f), CLIP_W);
            o.w = fminf(fmaxf(pcy + 0.5f * ph - 1.0f, 0.0f), CLIP_H);
            g_cboxes4[g] = o;
            g_cscore[g] = score;
        }
    }
}

// ---------------- stage 3: block-per-class direct greedy NMS (R6, 57us) -------
// 512 threads/class: each round suppresses in parallel (<=2 IoUs/thread),
// warp 0 finds the next live index, early stop at 100 kept (pigeonhole: only
// the first 100 kept per class can reach the global top-100).
__global__ void __launch_bounds__(512) nms_kernel() {
    __shared__ float4 sbox[TOPKC];
    __shared__ float  sarea[TOPKC];
    __shared__ float  sscore[TOPKC];
    __shared__ ull    salive[16];
    __shared__ int    snext;
    __shared__ int    skept[100];
    int c = blockIdx.x, tid = threadIdx.x;

    if (tid < 16) salive[tid] = 0ull;
    __syncthreads();

    for (int base = 0; base < TOPKC; base += 512) {
        int i = base + tid;
        float s = -1.0f;
        if (i < TOPKC) {
            float4 b = g_cboxes4[c * TOPKC + i];
            sbox[i] = b;
            sarea[i] = (b.z - b.x + 1.0f) * (b.w - b.y + 1.0f);
            s = g_cscore[c * TOPKC + i];
            sscore[i] = s;
        }
        unsigned ball = __ballot_sync(0xffffffffu, s > SCORE_TH);
        if ((tid & 31) == 0 && ball)
            atomicOr(&salive[i >> 6], (ull)ball << (i & 32));
    }
    __syncthreads();

    int nk = 0, cur = -1;
    while (true) {
        if (tid < 32) {
            ull w = (tid < 16) ? salive[tid] : 0ull;
            int cw = (cur >= 0) ? (cur >> 6) : -1;
            if ((int)tid < cw) w = 0ull;
            else if ((int)tid == cw) w &= ~((2ull << (cur & 63)) - 1ull);
            unsigned ball = __ballot_sync(0xffffffffu, w != 0ull);
            int nxt = TOPKC;
            if (ball) {
                int ws = __ffs(ball) - 1;
                ull lv = __shfl_sync(0xffffffffu, w, ws);
                nxt = (ws << 6) + __ffsll((long long)lv) - 1;
            }
            if (tid == 0) snext = nxt;
        }
        __syncthreads();
        cur = snext;
        if (cur >= TOPKC || nk >= 100) break;
        if (tid == 0) skept[nk] = cur;
        nk++;
        float4 bi = sbox[cur];
        float  ai = sarea[cur];
        for (int j = cur + 1 + tid; j < TOPKC; j += 512) {
            float4 bj = sbox[j];
            float iw = fminf(bi.z, bj.z) - fmaxf(bi.x, bj.x) + 1.0f;
            float ih = fminf(bi.w, bj.w) - fmaxf(bi.y, bj.y) + 1.0f;
            if (iw > 0.0f && ih > 0.0f) {
                float inter = iw * ih;
                if (3.0f * inter > ai + sarea[j])       // iou > 0.5
                    atomicAnd(&salive[j >> 6], ~(1ull << (j & 63)));
            }
        }
        __syncthreads();
    }

    if (tid < 100) {
        ull key = 0ull;
        if (tid < nk) {
            int i = skept[tid];
            int flat = c * TOPKC + i;
            key = ((ull)__float_as_uint(sscore[i]) << 32) | (unsigned)(~flat);
        }
        g_merge[c * 100 + tid] = key;
    }
}

// ---------------- stage 4: global top-100 via histogram-select + rank ---------
#define MERGE_SMEM (9000*8 + 1024*4 + 1024*8 + 16)
__global__ void __launch_bounds__(1024) merge_kernel(float* __restrict__ out) {
    extern __shared__ unsigned char msm[];
    ull* sk    = (ull*)msm;                 // 9000 keys
    int* hist  = (int*)(sk + 9000);         // 1024 buckets
    ull* ssel  = (ull*)(hist + 1024);       // selected (<=1024)
    int* sinfo = (int*)(ssel + 1024);       // [0]=B, [1]=scnt
    int tid = threadIdx.x;

    for (int t = tid; t < NFG * 100; t += 1024) sk[t] = g_merge[t];
    hist[tid] = 0;
    if (tid == 0) { sinfo[0] = 0; sinfo[1] = 0; }
    __syncthreads();

    for (int t = tid; t < NFG * 100; t += 1024) {
        ull k = sk[t];
        if (k) {
            int b = (int)(k >> 48) - 0x3D00;
            b = max(0, min(1023, b));
            atomicAdd(&hist[b], 1);
        }
    }
    __syncthreads();

    if (tid < 32) {
        int base = 1023 - tid * 32;
        int lsum = 0;
        #pragma unroll
        for (int q = 0; q < 32; q++) lsum += hist[base - q];
        int incl = lsum;
        #pragma unroll
        for (int d = 1; d < 32; d <<= 1) {
            int v = __shfl_up_sync(0xffffffffu, incl, d);
            if (tid >= d) incl += v;
        }
        int excl = incl - lsum;
        bool has = (excl < 100) && (excl + lsum >= 100);
        unsigned ball = __ballot_sync(0xffffffffu, has);
        if (ball) {
            int selLane = __ffs(ball) - 1;
            if ((int)tid == selLane) {
                int cum = excl, b = base;
                for (int q = 0; q < 32; q++) {
                    cum += hist[base - q];
                    if (cum >= 100) { b = base - q; break; }
                }
                sinfo[0] = b;
            }
        }
    }
    __syncthreads();

    int B = sinfo[0];
    for (int t = tid; t < NFG * 100; t += 1024) {
        ull k = sk[t];
        if (k) {
            int b = (int)(k >> 48) - 0x3D00;
            b = max(0, min(1023, b));
            if (b >= B) {
                int pos = atomicAdd(&sinfo[1], 1);
                if (pos < 1024) ssel[pos] = k;
            }
        }
    }
    __syncthreads();

    int scnt = min(sinfo[1], 1024);
    if (tid < scnt) {
        ull my = ssel[tid];
        int cnt = 0;
        for (int x = 0; x < scnt; x++) cnt += (ssel[x] > my);
        if (cnt < 100) {                     // exact global rank (keys unique)
            int flat = (int)(~(unsigned)(my & 0xffffffffu));
            float sc = __uint_as_float((unsigned)(my >> 32));
            float4 b = g_cboxes4[flat];
            out[cnt * 4 + 0] = b.x;
            out[cnt * 4 + 1] = b.y;
            out[cnt * 4 + 2] = b.z;
            out[cnt * 4 + 3] = b.w;
            out[400 + cnt] = sc;
            out[500 + cnt] = (float)(flat / TOPKC + 1);
        }
    }
}

// ---------------- launch ----------------
extern "C" void kernel_launch(void* const* d_in, const int* in_sizes, int n_in,
                              void* d_out, int out_size) {
    const float* logits = nullptr;
    const float* reg    = nullptr;
    const float* prop   = nullptr;
    for (int i = 0; i < n_in; i++) {
        if (in_sizes[i] == N_PROPS * NCLS)          logits = (const float*)d_in[i];
        else if (in_sizes[i] == N_PROPS * NCLS * 4) reg    = (const float*)d_in[i];
        else if (in_sizes[i] == N_PROPS * 4)        prop   = (const float*)d_in[i];
    }
    if (!logits) logits = (const float*)d_in[0];
    if (!reg)    reg    = (const float*)d_in[1];
    if (!prop)   prop   = (const float*)d_in[2];

    cudaFuncSetAttribute(sortselect_kernel,
                         cudaFuncAttributeMaxDynamicSharedMemorySize, SORT_SMEM);
    cudaFuncSetAttribute(merge_kernel,
                         cudaFuncAttributeMaxDynamicSharedMemorySize, MERGE_SMEM);

    init_kernel<<<1, 640>>>((float*)d_out);
    softmax_compact_kernel<<<N_PROPS / 32, 256>>>(logits);
    sortselect_kernel<<<NFG, 1024, SORT_SMEM>>>(reg, prop);
    nms_kernel<<<NFG, 512>>>();
    merge_kernel<<<1, 1024, MERGE_SMEM>>>((float*)d_out);
}

// round 13
// speedup vs baseline: 2.9180x; 1.5560x over previous
#include <cuda_runtime.h>

#define N_PROPS   100000
#define NCLS      91
#define NFG       90
#define CAPC      8192
#define TOPKC     1000
#define SCORE_TH  0.05f
#define CLIP_W    1332.0f
#define CLIP_H    799.0f
#define XFORM_CLIP 4.135166556742356f   // log(1000/16)

typedef unsigned long long ull;

// ---------------- scratch ----------------
__device__ ull    g_cand  [NFG * CAPC];
__device__ int    g_count [NFG];
__device__ float4 g_cboxes4[NFG * TOPKC];
__device__ ull    g_merge [NFG * 100];

// ---------------- stage 0: per-replay init ----------------
__global__ void init_kernel(float* __restrict__ out) {
    int t = threadIdx.x;
    if (t < NFG) g_count[t] = 0;
    if (t < 600) out[t] = (t >= 400 && t < 500) ? -1.0f : 0.0f;
}

// ---------------- stage 1: softmax + compaction with block-level staging ------
// 1024 threads / 128 rows per block. Candidates stage in smem per class; ONE
// gmem atomicAdd per (class, block) instead of one per (class, warp-round):
// 781 vs 2200 same-address L2 atomics per class (the measured bottleneck).
#define SM_ROWS 128
#define STGCAP  24
#define SMAX_SMEM (SM_ROWS*93*4 + SM_ROWS*4 + NFG*STGCAP*8 + NFG*4 + 16)
__global__ void __launch_bounds__(1024) softmax_compact_kernel(
        const float* __restrict__ logits) {
    extern __shared__ unsigned char sraw[];
    float* sm     = (float*)sraw;                    // [128][93] (93: bank-free)
    float* sinv   = sm + SM_ROWS * 93;               // [128]
    ull*   stg    = (ull*)(sinv + SM_ROWS);          // [90][STGCAP]
    int*   scount = (int*)(stg + NFG * STGCAP);      // [90]

    int tid = threadIdx.x;
    int base = blockIdx.x * SM_ROWS;
    if (tid < NFG) scount[tid] = 0;

    for (int t = tid; t < SM_ROWS * 91; t += 1024) {
        int r = t / 91, c = t - r * 91;
        int gr = base + r;
        sm[r * 93 + c] = (gr < N_PROPS) ? logits[gr * 91 + c] : 0.0f;
    }
    __syncthreads();

    int warp = tid >> 5, lane = tid & 31;
    for (int r = warp; r < SM_ROWS; r += 32) {
        float e0 = __expf(sm[r * 93 + lane]);
        float e1 = __expf(sm[r * 93 + lane + 32]);
        float e2 = (lane < 27) ? __expf(sm[r * 93 + lane + 64]) : 0.0f;
        sm[r * 93 + lane]      = e0;
        sm[r * 93 + lane + 32] = e1;
        if (lane < 27) sm[r * 93 + lane + 64] = e2;
        float sum = e0 + e1 + e2;
        #pragma unroll
        for (int d = 16; d > 0; d >>= 1)
            sum += __shfl_xor_sync(0xffffffffu, sum, d);
        if (lane == 0) sinv[r] = 1.0f / sum;
    }
    __syncthreads();

    // stage candidates in smem (class uniform per warp; r == r0 + lane)
    for (int t = tid; t < NFG * SM_ROWS; t += 1024) {
        int c = t >> 7;          // fg class 0..89, uniform across warp
        int r = t & 127;
        float v = sm[r * 93 + c + 1] * sinv[r];
        bool p = (v > SCORE_TH) && (base + r < N_PROPS);
        unsigned ball = __ballot_sync(0xffffffffu, p);
        int lpos = 0;
        if (lane == 0 && ball) lpos = atomicAdd(&scount[c], __popc(ball));
        lpos = __shfl_sync(0xffffffffu, lpos, 0);
        if (p) {
            int mypos = lpos + __popc(ball & ((1u << lane) - 1u));
            ull key = ((ull)__float_as_uint(v) << 32) | (unsigned)(~(base + r));
            if (mypos < STGCAP) {
                stg[c * STGCAP + mypos] = key;
            } else {                               // rare overflow: direct path
                int gp = atomicAdd(&g_count[c], 1);
                if (gp < CAPC) g_cand[c * CAPC + gp] = key;
            }
        }
    }
    __syncthreads();

    // flush staged candidates: one gmem atomic per class per block
    for (int c = warp; c < NFG; c += 32) {
        int cnt = min(scount[c], STGCAP);
        if (cnt) {
            int gbase = 0;
            if (lane == 0) gbase = atomicAdd(&g_count[c], cnt);
            gbase = __shfl_sync(0xffffffffu, gbase, 0);
            if (lane < cnt) {
                int gp = gbase + lane;
                if (gp < CAPC) g_cand[c * CAPC + gp] = stg[c * STGCAP + lane];
            }
        }
    }
}

// ---------------- stage 2: fused select + sort + decode + NMS (per class) -----
// histogram-select top-~1000 superset -> small bitonic -> decode into smem SoA
// -> greedy NMS with all-threads find-next (no serial warp-0 section),
// early stop at 100 kept (pigeonhole: only first 100 kept can reach top-100).
#define FUSE_SMEM (CAPC*8 + 1024*4 + 8 + 6*TOPKC*4 + 16*8 + 101*4 + 16)
__global__ void __launch_bounds__(1024) sortnms_kernel(
        const float* __restrict__ reg, const float* __restrict__ prop) {
    extern __shared__ unsigned char fsm[];
    ull*   sk     = (ull*)fsm;                       // [CAPC]
    int*   hist   = (int*)(sk + CAPC);               // [1024]
    int*   sinfo  = hist + 1024;                     // [0]=B, [1]=selcnt
    float* sx1    = (float*)(sinfo + 2);             // [1000] x6 SoA
    float* sy1    = sx1 + TOPKC;
    float* sx2    = sy1 + TOPKC;
    float* sy2    = sx2 + TOPKC;
    float* sar    = sy2 + TOPKC;
    float* ssc    = sar + TOPKC;
    ull*   salive = (ull*)(ssc + TOPKC);             // [16]
    int*   skept  = (int*)(salive + 16);             // [100]

    int c = blockIdx.x, tid = threadIdx.x;
    int count = min(g_count[c], CAPC);
    int want  = min(count, TOPKC);

    hist[tid] = 0;
    if (tid == 0) { sinfo[0] = 0; sinfo[1] = 0; }
    if (tid < 16) salive[tid] = 0ull;
    __syncthreads();

    for (int t = tid; t < count; t += 1024) {
        ull k = g_cand[c * CAPC + t];
        int b = (int)(k >> 48) - 0x3D00;
        b = max(0, min(1023, b));
        atomicAdd(&hist[b], 1);
    }
    __syncthreads();

    // warp 0: highest bucket B with suffix-count >= want
    if (tid < 32) {
        int base = 1023 - tid * 32;
        int lsum = 0;
        #pragma unroll
        for (int q = 0; q < 32; q++) lsum += hist[base - q];
        int incl = lsum;
        #pragma unroll
        for (int d = 1; d < 32; d <<= 1) {
            int v = __shfl_up_sync(0xffffffffu, incl, d);
            if (tid >= d) incl += v;
        }
        int excl = incl - lsum;
        bool has = (excl < want) && (excl + lsum >= want);
        unsigned ball = __ballot_sync(0xffffffffu, has);
        if (ball) {
            int selLane = __ffs(ball) - 1;
            if ((int)tid == selLane) {
                int cum = excl, b = base;
                for (int q = 0; q < 32; q++) {
                    cum += hist[base - q];
                    if (cum >= want) { b = base - q; break; }
                }
                sinfo[0] = b;
            }
        }
    }
    __syncthreads();

    int B = sinfo[0];
    for (int t = tid; t < count; t += 1024) {
        ull k = g_cand[c * CAPC + t];
        int b = (int)(k >> 48) - 0x3D00;
        b = max(0, min(1023, b));
        if (b >= B) {
            int p = atomicAdd(&sinfo[1], 1);
            sk[p] = k;                 // p < count <= CAPC always
        }
    }
    __syncthreads();

    int selcnt = sinfo[1];
    int S = 1024;
    while (S < selcnt) S <<= 1;
    for (int t = tid; t < S; t += 1024)
        if (t >= selcnt) sk[t] = 0ull;
    __syncthreads();

    for (int k = 2; k <= S; k <<= 1) {
        for (int j = k >> 1; j > 0; j >>= 1) {
            for (int t = tid; t < S; t += 1024) {
                int ixj = t ^ j;
                if (ixj > t) {
                    ull a = sk[t], b = sk[ixj];
                    bool up = (t & k) == 0;
                    if (up ? (a < b) : (a > b)) { sk[t] = b; sk[ixj] = a; }
                }
            }
            __syncthreads();
        }
    }

    // decode top-1000 into smem SoA (+ g_cboxes4 for merge-stage lookup)
    float s = -1.0f;
    if (tid < TOPKC) {
        ull key = sk[tid];
        int g = c * TOPKC + tid;
        if (key == 0ull) {
            sx1[tid] = 0.f; sy1[tid] = 0.f; sx2[tid] = 0.f; sy2[tid] = 0.f;
            sar[tid] = 1.0f; ssc[tid] = -1.0f;
            g_cboxes4[g] = make_float4(0.f, 0.f, 0.f, 0.f);
        } else {
            unsigned idx = ~(unsigned)(key & 0xffffffffu);
            s = __uint_as_float((unsigned)(key >> 32));
            const float* pb = prop + (size_t)idx * 4;
            float x1 = pb[0], y1 = pb[1], x2 = pb[2], y2 = pb[3];
            float w = x2 - x1 + 1.0f, h = y2 - y1 + 1.0f;
            float cx = x1 + 0.5f * w, cy = y1 + 0.5f * h;
            const float* d = reg + (size_t)idx * (NCLS * 4) + (size_t)(c + 1) * 4;
            float dx = d[0] * 0.1f;
            float dy = d[1] * 0.1f;
            float dw = fminf(d[2] * 0.2f, XFORM_CLIP);
            float dh = fminf(d[3] * 0.2f, XFORM_CLIP);
            float pcx = dx * w + cx, pcy = dy * h + cy;
            float pw = __expf(dw) * w, ph = __expf(dh) * h;
            float ox = fminf(fmaxf(pcx - 0.5f * pw, 0.0f), CLIP_W);
            float oy = fminf(fmaxf(pcy - 0.5f * ph, 0.0f), CLIP_H);
            float oz = fminf(fmaxf(pcx + 0.5f * pw - 1.0f, 0.0f), CLIP_W);
            float ow = fminf(fmaxf(pcy + 0.5f * ph - 1.0f, 0.0f), CLIP_H);
            sx1[tid] = ox; sy1[tid] = oy; sx2[tid] = oz; sy2[tid] = ow;
            sar[tid] = (oz - ox + 1.0f) * (ow - oy + 1.0f);
            ssc[tid] = s;
            g_cboxes4[g] = make_float4(ox, oy, oz, ow);
        }
    }
    // alive bits
    {
        unsigned ball = __ballot_sync(0xffffffffu, s > SCORE_TH);
        if ((tid & 31) == 0 && ball)
            atomicOr(&salive[tid >> 6], (ull)ball << (tid & 32));
    }
    __syncthreads();

    // greedy NMS: all threads find-next redundantly (deterministic), 2 bars/round
    int nk = 0, cur = -1;
    while (nk < 100) {
        int w = (cur >= 0) ? (cur >> 6) : 0;
        ull mask = (cur >= 0) ? ~((2ull << (cur & 63)) - 1ull) : ~0ull;
        int nxt = TOPKC;
        for (; w < 16; w++) {
            ull m = salive[w] & mask;
            mask = ~0ull;
            if (m) { nxt = (w << 6) + __ffsll((long long)m) - 1; break; }
        }
        if (nxt >= TOPKC) break;
        cur = nxt;
        if (tid == 0) skept[nk] = cur;
        nk++;
        float cx1 = sx1[cur], cy1 = sy1[cur];
        float cx2 = sx2[cur], cy2 = sy2[cur];
        float ac  = sar[cur];
        __syncthreads();                 // everyone done reading salive
        int j = cur + 1 + tid;
        if (j < TOPKC) {
            float iw = fminf(cx2, sx2[j]) - fmaxf(cx1, sx1[j]) + 1.0f;
            float ih = fminf(cy2, sy2[j]) - fmaxf(cy1, sy1[j]) + 1.0f;
            if (iw > 0.0f && ih > 0.0f) {
                float inter = iw * ih;
                if (3.0f * inter > ac + sar[j])        // iou > 0.5
                    atomicAnd(&salive[j >> 6], ~(1ull << (j & 63)));
            }
        }
        __syncthreads();                 // suppression visible
    }
    __syncthreads();

    if (tid < 100) {
        ull key = 0ull;
        if (tid < nk) {
            int i = skept[tid];
            int flat = c * TOPKC + i;
            key = ((ull)__float_as_uint(ssc[i]) << 32) | (unsigned)(~flat);
        }
        g_merge[c * 100 + tid] = key;
    }
}

// ---------------- stage 3: global top-100 via histogram-select + rank ---------
#define MERGE_SMEM (9000*8 + 1024*4 + 1024*8 + 16)
__global__ void __launch_bounds__(1024) merge_kernel(float* __restrict__ out) {
    extern __shared__ unsigned char msm[];
    ull* sk    = (ull*)msm;                 // 9000 keys
    int* hist  = (int*)(sk + 9000);         // 1024 buckets
    ull* ssel  = (ull*)(hist + 1024);       // selected (<=1024)
    int* sinfo = (int*)(ssel + 1024);       // [0]=B, [1]=scnt
    int tid = threadIdx.x;

    for (int t = tid; t < NFG * 100; t += 1024) sk[t] = g_merge[t];
    hist[tid] = 0;
    if (tid == 0) { sinfo[0] = 0; sinfo[1] = 0; }
    __syncthreads();

    for (int t = tid; t < NFG * 100; t += 1024) {
        ull k = sk[t];
        if (k) {
            int b = (int)(k >> 48) - 0x3D00;
            b = max(0, min(1023, b));
            atomicAdd(&hist[b], 1);
        }
    }
    __syncthreads();

    if (tid < 32) {
        int base = 1023 - tid * 32;
        int lsum = 0;
        #pragma unroll
        for (int q = 0; q < 32; q++) lsum += hist[base - q];
        int incl = lsum;
        #pragma unroll
        for (int d = 1; d < 32; d <<= 1) {
            int v = __shfl_up_sync(0xffffffffu, incl, d);
            if (tid >= d) incl += v;
        }
        int excl = incl - lsum;
        bool has = (excl < 100) && (excl + lsum >= 100);
        unsigned ball = __ballot_sync(0xffffffffu, has);
        if (ball) {
            int selLane = __ffs(ball) - 1;
            if ((int)tid == selLane) {
                int cum = excl, b = base;
                for (int q = 0; q < 32; q++) {
                    cum += hist[base - q];
                    if (cum >= 100) { b = base - q; break; }
                }
                sinfo[0] = b;
            }
        }
    }
    __syncthreads();

    int B = sinfo[0];
    for (int t = tid; t < NFG * 100; t += 1024) {
        ull k = sk[t];
        if (k) {
            int b = (int)(k >> 48) - 0x3D00;
            b = max(0, min(1023, b));
            if (b >= B) {
                int pos = atomicAdd(&sinfo[1], 1);
                if (pos < 1024) ssel[pos] = k;
            }
        }
    }
    __syncthreads();

    int scnt = min(sinfo[1], 1024);
    if (tid < scnt) {
        ull my = ssel[tid];
        int cnt = 0;
        for (int x = 0; x < scnt; x++) cnt += (ssel[x] > my);
        if (cnt < 100) {                     // exact global rank (keys unique)
            int flat = (int)(~(unsigned)(my & 0xffffffffu));
            float sc = __uint_as_float((unsigned)(my >> 32));
            float4 b = g_cboxes4[flat];
            out[cnt * 4 + 0] = b.x;
            out[cnt * 4 + 1] = b.y;
            out[cnt * 4 + 2] = b.z;
            out[cnt * 4 + 3] = b.w;
            out[400 + cnt] = sc;
            out[500 + cnt] = (float)(flat / TOPKC + 1);
        }
    }
}

// ---------------- launch ----------------
extern "C" void kernel_launch(void* const* d_in, const int* in_sizes, int n_in,
                              void* d_out, int out_size) {
    const float* logits = nullptr;
    const float* reg    = nullptr;
    const float* prop   = nullptr;
    for (int i = 0; i < n_in; i++) {
        if (in_sizes[i] == N_PROPS * NCLS)          logits = (const float*)d_in[i];
        else if (in_sizes[i] == N_PROPS * NCLS * 4) reg    = (const float*)d_in[i];
        else if (in_sizes[i] == N_PROPS * 4)        prop   = (const float*)d_in[i];
    }
    if (!logits) logits = (const float*)d_in[0];
    if (!reg)    reg    = (const float*)d_in[1];
    if (!prop)   prop   = (const float*)d_in[2];

    cudaFuncSetAttribute(softmax_compact_kernel,
                         cudaFuncAttributeMaxDynamicSharedMemorySize, SMAX_SMEM);
    cudaFuncSetAttribute(sortnms_kernel,
                         cudaFuncAttributeMaxDynamicSharedMemorySize, FUSE_SMEM);
    cudaFuncSetAttribute(merge_kernel,
                         cudaFuncAttributeMaxDynamicSharedMemorySize, MERGE_SMEM);

    int smax_grid = (N_PROPS + SM_ROWS - 1) / SM_ROWS;   // 782
    init_kernel<<<1, 640>>>((float*)d_out);
    softmax_compact_kernel<<<smax_grid, 1024, SMAX_SMEM>>>(logits);
    sortnms_kernel<<<NFG, 1024, FUSE_SMEM>>>(reg, prop);
    merge_kernel<<<1, 1024, MERGE_SMEM>>>((float*)d_out);
}